// round 12
// baseline (speedup 1.0000x reference)
#include <cuda_runtime.h>
#include <cuda_bf16.h>
#include <cstdint>

// Fixed shapes for TemporalGCN_19232863551793
#define TT   2
#define NN   50000
#define EE   800000
#define CC   128          // IN_C == HID == 128
#define CAP  192          // per-node incoming-edge bucket capacity (Poisson(16) input)

// ---------------- device scratch (no allocs allowed) ----------------
__device__ int   g_is64;                          // 1 if edge buffer is int64, 0 if int32
__device__ int   g_cnt [NN];
__device__ float g_dinv[NN];
__device__ int   g_bucket[(size_t)NN * CAP];      // src ids per dst
__device__ float g_h   [(size_t)NN * CC];         // GEMM output (pre-norm/bias)
__device__ float g_hb  [(size_t)NN * CC];         // conv1 output

// ---------------- dtype probe ----------------
// View the edge buffer as int32. If it is really int64 with values < 2^31,
// every odd 32-bit word (high half, little-endian) is 0. If it is int32 of
// random node ids, odd words are random. Reads only the first 2048 int32s
// (8 KB), in-bounds for both interpretations.
__global__ void probe_dtype_kernel(const int* __restrict__ e32) {
    __shared__ int nz;
    if (threadIdx.x == 0) nz = 0;
    __syncthreads();
    int acc = 0;
    for (int k = threadIdx.x; k < 1024; k += blockDim.x)
        acc |= e32[2 * k + 1];
    if (acc) atomicOr(&nz, 1);
    __syncthreads();
    if (threadIdx.x == 0) g_is64 = (nz == 0) ? 1 : 0;
}

// ---------------- CSR-by-dst build ----------------
__global__ void zero_cnt_kernel() {
    int i = blockIdx.x * blockDim.x + threadIdx.x;
    if (i < NN) g_cnt[i] = 0;
}

// eidx points at the full [T, 2, E] buffer; t selects the timestep.
__global__ void bucket_fill_kernel(const void* __restrict__ eidx, int t) {
    int e = blockIdx.x * blockDim.x + threadIdx.x;
    if (e >= EE) return;
    int s, d;
    if (g_is64) {
        const long long* p = (const long long*)eidx + (size_t)t * 2 * EE;
        s = (int)p[e];
        d = (int)p[e + EE];
    } else {
        const int* p = (const int*)eidx + (size_t)t * 2 * EE;
        s = p[e];
        d = p[e + EE];
    }
    if ((unsigned)s >= NN || (unsigned)d >= NN) return;   // defensive
    int pos = atomicAdd(&g_cnt[d], 1);
    if (pos < CAP) g_bucket[(size_t)d * CAP + pos] = s;
}

__global__ void finalize_dinv_kernel() {
    int i = blockIdx.x * blockDim.x + threadIdx.x;
    if (i < NN) g_dinv[i] = rsqrtf((float)g_cnt[i] + 1.0f);   // +1 self-loop; > 0
}

// ---------------- GEMM: Out[N,128] = A[N,128] @ W[128,128], optional ReLU on A load ----------------
template <bool RELU>
__global__ void gemm128_kernel(const float* __restrict__ A,
                               const float* __restrict__ W,
                               float* __restrict__ Out, int n) {
    __shared__ float As[64][33];
    __shared__ float Bs[32][132];

    const int tid = threadIdx.x;      // 256 threads
    const int ty  = tid >> 4;         // 0..15  -> 4 rows each
    const int tx  = tid & 15;         // 0..15  -> 8 cols each
    const int row0 = blockIdx.x * 64;

    float acc[4][8];
#pragma unroll
    for (int i = 0; i < 4; i++)
#pragma unroll
        for (int j = 0; j < 8; j++) acc[i][j] = 0.0f;

    for (int k0 = 0; k0 < 128; k0 += 32) {
        for (int i = tid; i < 64 * 32; i += 256) {
            int r = i >> 5, k = i & 31;
            float v = 0.0f;
            if (row0 + r < n) v = A[(size_t)(row0 + r) * CC + k0 + k];
            if (RELU) v = fmaxf(v, 0.0f);
            As[r][k] = v;
        }
        for (int i = tid; i < 32 * 128; i += 256) {
            int k = i >> 7, c = i & 127;
            Bs[k][c] = W[(size_t)(k0 + k) * CC + c];
        }
        __syncthreads();

#pragma unroll
        for (int k = 0; k < 32; k++) {
            float a[4], b[8];
#pragma unroll
            for (int i = 0; i < 4; i++) a[i] = As[ty * 4 + i][k];
#pragma unroll
            for (int j = 0; j < 8; j++) b[j] = Bs[k][tx * 8 + j];
#pragma unroll
            for (int i = 0; i < 4; i++)
#pragma unroll
                for (int j = 0; j < 8; j++) acc[i][j] += a[i] * b[j];
        }
        __syncthreads();
    }

#pragma unroll
    for (int i = 0; i < 4; i++) {
        int row = row0 + ty * 4 + i;
        if (row < n) {
            float* o = Out + (size_t)row * CC + tx * 8;
#pragma unroll
            for (int j = 0; j < 8; j++) o[j] = acc[i][j];
        }
    }
}

// ---------------- gather: one warp per dst node; no float atomics ----------------
// out[d,:] = sum_{e: dst=d} h[src_e,:] * dinv[src_e]*dinv[d]
//          + h[d,:] * dinv[d]^2        (self loop)
//          + b[:]
// If IMP: also imp[d] = dot(out[d,:], Wc) + bc
template <bool IMP>
__global__ void gather_kernel(const float* __restrict__ h,
                              const float* __restrict__ b,
                              float* __restrict__ out,
                              const float* __restrict__ Wc,
                              const float* __restrict__ bc,
                              float* __restrict__ imp) {
    int gtid = blockIdx.x * blockDim.x + threadIdx.x;
    int d    = gtid >> 5;
    int lane = gtid & 31;
    if (d >= NN) return;

    const float4* h4 = (const float4*)h;
    float dd  = g_dinv[d];
    float dd2 = dd * dd;
    int deg = g_cnt[d];
    if (deg > CAP) deg = CAP;

    // self-loop + bias init
    float4 acc = h4[(size_t)d * 32 + lane];
    float4 b4  = ((const float4*)b)[lane];
    acc.x = acc.x * dd2 + b4.x;
    acc.y = acc.y * dd2 + b4.y;
    acc.z = acc.z * dd2 + b4.z;
    acc.w = acc.w * dd2 + b4.w;

    size_t base = (size_t)d * CAP;
    for (int i0 = 0; i0 < deg; i0 += 32) {
        int idx = i0 + lane;
        int   myS = 0;
        float myN = 0.0f;
        if (idx < deg) {
            myS = g_bucket[base + idx];
            myN = g_dinv[myS];
        }
        int kk = deg - i0; if (kk > 32) kk = 32;
        for (int k = 0; k < kk; k++) {
            int   s   = __shfl_sync(0xFFFFFFFFu, myS, k);
            float nrm = __shfl_sync(0xFFFFFFFFu, myN, k) * dd;
            float4 v = h4[(size_t)s * 32 + lane];
            acc.x += v.x * nrm;
            acc.y += v.y * nrm;
            acc.z += v.z * nrm;
            acc.w += v.w * nrm;
        }
    }

    ((float4*)out)[(size_t)d * 32 + lane] = acc;

    if (IMP) {
        float4 w = ((const float4*)Wc)[lane];
        float sum = acc.x * w.x + acc.y * w.y + acc.z * w.z + acc.w * w.w;
#pragma unroll
        for (int o = 16; o > 0; o >>= 1) sum += __shfl_down_sync(0xFFFFFFFFu, sum, o);
        if (lane == 0) imp[d] = sum + bc[0];
    }
}

// ---------------- launch ----------------
extern "C" void kernel_launch(void* const* d_in, const int* in_sizes, int n_in,
                              void* d_out, int out_size) {
    const float* x_seq = (const float*)d_in[0];   // [T, N, 128]
    const void*  eidx  = d_in[1];                 // [T, 2, E] int32 or int64
    const float* W1    = (const float*)d_in[2];
    const float* b1    = (const float*)d_in[3];
    const float* W2    = (const float*)d_in[4];
    const float* b2    = (const float*)d_in[5];
    const float* Wc    = (const float*)d_in[6];
    const float* bc    = (const float*)d_in[7];

    float* out = (float*)d_out;
    // output layout: [importance (N)] [out_t0 (N*128)] [out_t1 (N*128)]
    float* imp = out;
    float* outs[TT];
    outs[0] = out + NN;
    outs[1] = out + NN + (size_t)NN * CC;

    float* hA = nullptr;  // GEMM scratch
    float* hB = nullptr;  // conv1 output scratch
    cudaGetSymbolAddress((void**)&hA, g_h);
    cudaGetSymbolAddress((void**)&hB, g_hb);

    const int nodeBlocks   = (NN + 255) / 256;                      // 196
    const int edgeBlocks   = (EE + 255) / 256;                      // 3125
    const int gemmBlocks   = (NN + 63) / 64;                        // 782
    const int gatherBlocks = (int)(((size_t)NN * 32 + 255) / 256);  // 6250

    // detect int32 vs int64 edge index dtype (writes g_is64)
    probe_dtype_kernel<<<1, 256>>>((const int*)eidx);

    for (int t = 0; t < TT; t++) {
        const float* x_t = x_seq + (size_t)t * NN * CC;

        // bucket edges by dst + dinv for this timestep
        zero_cnt_kernel<<<nodeBlocks, 256>>>();
        bucket_fill_kernel<<<edgeBlocks, 256>>>(eidx, t);
        finalize_dinv_kernel<<<nodeBlocks, 256>>>();

        // conv1: h = x @ W1 ; out1 = gather + self + b1  (relu fused into next GEMM's A load)
        gemm128_kernel<false><<<gemmBlocks, 256>>>(x_t, W1, hA, NN);
        gather_kernel<false><<<gatherBlocks, 256>>>(hA, b1, hB, Wc, bc, imp);

        // conv2: h2 = relu(out1) @ W2 ; out_t = gather + self + b2 (+ importance at final t)
        gemm128_kernel<true><<<gemmBlocks, 256>>>(hB, W2, hA, NN);
        if (t == TT - 1)
            gather_kernel<true ><<<gatherBlocks, 256>>>(hA, b2, outs[t], Wc, bc, imp);
        else
            gather_kernel<false><<<gatherBlocks, 256>>>(hA, b2, outs[t], Wc, bc, imp);
    }
}

// round 13
// speedup vs baseline: 1.5955x; 1.5955x over previous
#include <cuda_runtime.h>
#include <cuda_bf16.h>
#include <cstdint>

// Fixed shapes for TemporalGCN_19232863551793
#define TT   2
#define NN   50000
#define EE   800000
#define CC   128          // IN_C == HID == 128
#define CAP  192          // per-node incoming-edge bucket capacity (Poisson(16) input)

// ---------------- device scratch (no allocs allowed) ----------------
__device__ int   g_is64;                          // 1 if edge buffer is int64, 0 if int32
__device__ int   g_cnt [NN];
__device__ float g_dinv[NN];
__device__ int   g_bucket[(size_t)NN * CAP];      // src ids per dst
__device__ float g_h   [(size_t)NN * CC];         // GEMM output (pre-norm/bias)
__device__ float g_hb  [(size_t)NN * CC];         // conv1 output

// ---------------- dtype probe ----------------
__global__ void probe_dtype_kernel(const int* __restrict__ e32) {
    __shared__ int nz;
    if (threadIdx.x == 0) nz = 0;
    __syncthreads();
    int acc = 0;
    for (int k = threadIdx.x; k < 1024; k += blockDim.x)
        acc |= e32[2 * k + 1];
    if (acc) atomicOr(&nz, 1);
    __syncthreads();
    if (threadIdx.x == 0) g_is64 = (nz == 0) ? 1 : 0;
}

// ---------------- CSR-by-dst build ----------------
__global__ void zero_cnt_kernel() {
    int i = blockIdx.x * blockDim.x + threadIdx.x;
    if (i < NN) g_cnt[i] = 0;
}

__global__ void bucket_fill_kernel(const void* __restrict__ eidx, int t) {
    int e = blockIdx.x * blockDim.x + threadIdx.x;
    if (e >= EE) return;
    int s, d;
    if (g_is64) {
        const long long* p = (const long long*)eidx + (size_t)t * 2 * EE;
        s = (int)p[e];
        d = (int)p[e + EE];
    } else {
        const int* p = (const int*)eidx + (size_t)t * 2 * EE;
        s = p[e];
        d = p[e + EE];
    }
    if ((unsigned)s >= NN || (unsigned)d >= NN) return;   // defensive
    int pos = atomicAdd(&g_cnt[d], 1);
    if (pos < CAP) g_bucket[(size_t)d * CAP + pos] = s;
}

__global__ void finalize_dinv_kernel() {
    int i = blockIdx.x * blockDim.x + threadIdx.x;
    if (i < NN) g_dinv[i] = rsqrtf((float)g_cnt[i] + 1.0f);   // +1 self-loop; > 0
}

// ---------------- helpers ----------------
__device__ __forceinline__ uint32_t f2tf32(float v) {
    uint32_t r;
    asm("cvt.rna.tf32.f32 %0, %1;" : "=r"(r) : "f"(v));
    return r;
}

__device__ __forceinline__ void mma_tf32(float c[4],
                                         uint32_t a0, uint32_t a1, uint32_t a2, uint32_t a3,
                                         uint32_t b0, uint32_t b1) {
    asm volatile(
        "mma.sync.aligned.m16n8k8.row.col.f32.tf32.tf32.f32 "
        "{%0,%1,%2,%3}, {%4,%5,%6,%7}, {%8,%9}, {%0,%1,%2,%3};"
        : "+f"(c[0]), "+f"(c[1]), "+f"(c[2]), "+f"(c[3])
        : "r"(a0), "r"(a1), "r"(a2), "r"(a3), "r"(b0), "r"(b1));
}

// ---------------- tensor-core GEMM: Out[N,128] = A[N,128] @ W[128,128] ----------------
// 3-MMA tf32 split precision (fp32-accurate). Block: 128 rows x 128 cols, 8 warps.
// Warp w owns rows [blk*128 + 16w, +16). K chunked by 32; W chunk split hi/lo in SMEM.
#define BP 136   // smem pitch: 136 % 32 == 8 -> conflict-free b-frag loads
template <bool RELU>
__global__ __launch_bounds__(256, 2)
void gemm128_tc_kernel(const float* __restrict__ A,
                       const float* __restrict__ W,
                       float* __restrict__ Out, int n) {
    __shared__ float Bh[32][BP];
    __shared__ float Bl[32][BP];

    const int tid  = threadIdx.x;       // 256
    const int w    = tid >> 5;          // warp 0..7
    const int lane = tid & 31;
    const int g    = lane >> 2;         // 0..7
    const int t4   = lane & 3;          // 0..3
    const int rowbase = blockIdx.x * 128 + w * 16;
    const int r0 = rowbase + g;
    const int r1 = rowbase + g + 8;
    const bool v0 = (r0 < n);
    const bool v1 = (r1 < n);

    float c[16][4];
#pragma unroll
    for (int j = 0; j < 16; j++)
#pragma unroll
        for (int i = 0; i < 4; i++) c[j][i] = 0.0f;

    for (int k0 = 0; k0 < 128; k0 += 32) {
        __syncthreads();
        // cooperative load + hi/lo split of W chunk [k0..k0+32) x 128
        for (int i = tid; i < 32 * 128; i += 256) {
            int k = i >> 7, nn = i & 127;
            float v  = W[(size_t)(k0 + k) * CC + nn];
            float hv = __uint_as_float(f2tf32(v));
            Bh[k][nn] = hv;
            Bl[k][nn] = __uint_as_float(f2tf32(v - hv));
        }
        __syncthreads();

#pragma unroll
        for (int ks = 0; ks < 32; ks += 8) {
            // A fragment from global (read-once, L2-resident), ReLU fused, split hi/lo
            int kc = k0 + ks + t4;
            float a0 = 0.f, a1 = 0.f, a2 = 0.f, a3 = 0.f;
            if (v0) { a0 = A[(size_t)r0 * CC + kc]; a2 = A[(size_t)r0 * CC + kc + 4]; }
            if (v1) { a1 = A[(size_t)r1 * CC + kc]; a3 = A[(size_t)r1 * CC + kc + 4]; }
            if (RELU) {
                a0 = fmaxf(a0, 0.f); a1 = fmaxf(a1, 0.f);
                a2 = fmaxf(a2, 0.f); a3 = fmaxf(a3, 0.f);
            }
            uint32_t ah0 = f2tf32(a0), ah1 = f2tf32(a1), ah2 = f2tf32(a2), ah3 = f2tf32(a3);
            uint32_t al0 = f2tf32(a0 - __uint_as_float(ah0));
            uint32_t al1 = f2tf32(a1 - __uint_as_float(ah1));
            uint32_t al2 = f2tf32(a2 - __uint_as_float(ah2));
            uint32_t al3 = f2tf32(a3 - __uint_as_float(ah3));

#pragma unroll
            for (int j = 0; j < 16; j++) {
                uint32_t bh0 = __float_as_uint(Bh[ks + t4    ][8 * j + g]);
                uint32_t bh1 = __float_as_uint(Bh[ks + t4 + 4][8 * j + g]);
                uint32_t bl0 = __float_as_uint(Bl[ks + t4    ][8 * j + g]);
                uint32_t bl1 = __float_as_uint(Bl[ks + t4 + 4][8 * j + g]);
                mma_tf32(c[j], ah0, ah1, ah2, ah3, bh0, bh1);  // hi*hi
                mma_tf32(c[j], ah0, ah1, ah2, ah3, bl0, bl1);  // hi*lo
                mma_tf32(c[j], al0, al1, al2, al3, bh0, bh1);  // lo*hi
            }
        }
    }

    // store: float2 per (row, n-tile); 4 lanes cover 32B contiguous
    if (v0) {
        float* o = Out + (size_t)r0 * CC;
#pragma unroll
        for (int j = 0; j < 16; j++)
            *(float2*)(o + 8 * j + 2 * t4) = make_float2(c[j][0], c[j][1]);
    }
    if (v1) {
        float* o = Out + (size_t)r1 * CC;
#pragma unroll
        for (int j = 0; j < 16; j++)
            *(float2*)(o + 8 * j + 2 * t4) = make_float2(c[j][2], c[j][3]);
    }
}

// ---------------- gather: one warp per dst node; no float atomics ----------------
template <bool IMP>
__global__ void gather_kernel(const float* __restrict__ h,
                              const float* __restrict__ b,
                              float* __restrict__ out,
                              const float* __restrict__ Wc,
                              const float* __restrict__ bc,
                              float* __restrict__ imp) {
    int gtid = blockIdx.x * blockDim.x + threadIdx.x;
    int d    = gtid >> 5;
    int lane = gtid & 31;
    if (d >= NN) return;

    const float4* h4 = (const float4*)h;
    float dd  = g_dinv[d];
    float dd2 = dd * dd;
    int deg = g_cnt[d];
    if (deg > CAP) deg = CAP;

    // self-loop + bias init
    float4 acc = h4[(size_t)d * 32 + lane];
    float4 b4  = ((const float4*)b)[lane];
    acc.x = acc.x * dd2 + b4.x;
    acc.y = acc.y * dd2 + b4.y;
    acc.z = acc.z * dd2 + b4.z;
    acc.w = acc.w * dd2 + b4.w;

    size_t base = (size_t)d * CAP;
    for (int i0 = 0; i0 < deg; i0 += 32) {
        int idx = i0 + lane;
        int   myS = 0;
        float myN = 0.0f;
        if (idx < deg) {
            myS = g_bucket[base + idx];
            myN = g_dinv[myS];
        }
        int kk = deg - i0; if (kk > 32) kk = 32;
        for (int k = 0; k < kk; k++) {
            int   s   = __shfl_sync(0xFFFFFFFFu, myS, k);
            float nrm = __shfl_sync(0xFFFFFFFFu, myN, k) * dd;
            float4 v = h4[(size_t)s * 32 + lane];
            acc.x += v.x * nrm;
            acc.y += v.y * nrm;
            acc.z += v.z * nrm;
            acc.w += v.w * nrm;
        }
    }

    ((float4*)out)[(size_t)d * 32 + lane] = acc;

    if (IMP) {
        float4 w = ((const float4*)Wc)[lane];
        float sum = acc.x * w.x + acc.y * w.y + acc.z * w.z + acc.w * w.w;
#pragma unroll
        for (int o = 16; o > 0; o >>= 1) sum += __shfl_down_sync(0xFFFFFFFFu, sum, o);
        if (lane == 0) imp[d] = sum + bc[0];
    }
}

// ---------------- launch ----------------
extern "C" void kernel_launch(void* const* d_in, const int* in_sizes, int n_in,
                              void* d_out, int out_size) {
    const float* x_seq = (const float*)d_in[0];   // [T, N, 128]
    const void*  eidx  = d_in[1];                 // [T, 2, E] int32 (or int64; probed)
    const float* W1    = (const float*)d_in[2];
    const float* b1    = (const float*)d_in[3];
    const float* W2    = (const float*)d_in[4];
    const float* b2    = (const float*)d_in[5];
    const float* Wc    = (const float*)d_in[6];
    const float* bc    = (const float*)d_in[7];

    float* out = (float*)d_out;
    // output layout: [importance (N)] [out_t0 (N*128)] [out_t1 (N*128)]
    float* imp = out;
    float* outs[TT];
    outs[0] = out + NN;
    outs[1] = out + NN + (size_t)NN * CC;

    float* hA = nullptr;  // GEMM scratch
    float* hB = nullptr;  // conv1 output scratch
    cudaGetSymbolAddress((void**)&hA, g_h);
    cudaGetSymbolAddress((void**)&hB, g_hb);

    const int nodeBlocks   = (NN + 255) / 256;                      // 196
    const int edgeBlocks   = (EE + 255) / 256;                      // 3125
    const int gemmBlocks   = (NN + 127) / 128;                      // 391
    const int gatherBlocks = (int)(((size_t)NN * 32 + 255) / 256);  // 6250

    // detect int32 vs int64 edge index dtype (writes g_is64)
    probe_dtype_kernel<<<1, 256>>>((const int*)eidx);

    for (int t = 0; t < TT; t++) {
        const float* x_t = x_seq + (size_t)t * NN * CC;

        // bucket edges by dst + dinv for this timestep
        zero_cnt_kernel<<<nodeBlocks, 256>>>();
        bucket_fill_kernel<<<edgeBlocks, 256>>>(eidx, t);
        finalize_dinv_kernel<<<nodeBlocks, 256>>>();

        // conv1: h = x @ W1 ; out1 = gather + self + b1  (relu fused into next GEMM's A load)
        gemm128_tc_kernel<false><<<gemmBlocks, 256>>>(x_t, W1, hA, NN);
        gather_kernel<false><<<gatherBlocks, 256>>>(hA, b1, hB, Wc, bc, imp);

        // conv2: h2 = relu(out1) @ W2 ; out_t = gather + self + b2 (+ importance at final t)
        gemm128_tc_kernel<true><<<gemmBlocks, 256>>>(hB, W2, hA, NN);
        if (t == TT - 1)
            gather_kernel<true ><<<gatherBlocks, 256>>>(hA, b2, outs[t], Wc, bc, imp);
        else
            gather_kernel<false><<<gatherBlocks, 256>>>(hA, b2, outs[t], Wc, bc, imp);
    }
}